// round 7
// baseline (speedup 1.0000x reference)
#include <cuda_runtime.h>
#include <math.h>
#include <stdint.h>

#define BSZ   1024
#define NP    256
#define DIM   128
#define TB    51200      // triplets per batch segment (T1 == T3)
#define TL    12800      // triplets per lca segment   (T2 == T4)
#define TTOT  (2*TB + 2*TL)
#define NGBLK (TTOT / 8)

// ---------------- scratch (static device globals; no allocation) ------------
__device__ float  g_lh[NP * DIM];    // poincare-mapped lcas, row-major
__device__ float  g_lhT[DIM * NP];   // transposed for coalesced dist loads
__device__ float  g_y2[NP];          // ||lh||^2 per proxy
__device__ float  g_Dz[BSZ * NP];    // dist(z_s, lh)
__device__ float  g_Dt[BSZ * NP];    // dist(t_s, lh)
__device__ float  g_Dll[NP * NP];    // dist(lh, lh)
__device__ int    g_done = 0;        // poincare producer counter (reset by ghhc)

// ---------------- fused poincare + distance matrices -------------------------
// 288 blocks, 256 threads. Blocks 0..31 first compute the poincare map for
// proxies [b*8, b*8+8) (warp per row) and publish via g_done. Every block then
// spin-waits (thread 0) for all 32 producers before its dist tile.
// blocks: [0,128) -> z rows, [128,256) -> t rows, [256,288) -> lh rows.
__global__ __launch_bounds__(256) void k_dist_all(const float* __restrict__ lcas,
                                                  const float* __restrict__ z,
                                                  const float* __restrict__ t,
                                                  float* __restrict__ outp) {
    const int b    = blockIdx.x;
    const int tid  = threadIdx.x;
    const int warp = tid >> 5, lane = tid & 31;

    if (b == 0 && tid == 0) outp[0] = 0.0f;   // zero accumulator (ghhc adds later)

    // ---- producer phase: poincare map (blocks 0..31) ----
    if (b < 32) {
        const int r = b * 8 + warp;
        float x[4];
        #pragma unroll
        for (int q = 0; q < 4; ++q) x[q] = lcas[r * DIM + lane + 32 * q];

        float s = 0.0f;
        #pragma unroll
        for (int q = 0; q < 4; ++q) s = fmaf(x[q], x[q], s);
        #pragma unroll
        for (int off = 16; off > 0; off >>= 1) s += __shfl_xor_sync(0xffffffffu, s, off);
        float xn = sqrtf(s) + 1e-5f;

        float scale = fminf(1.0f, 2.3f / xn);
        #pragma unroll
        for (int q = 0; q < 4; ++q) x[q] *= scale;

        s = 0.0f;
        #pragma unroll
        for (int q = 0; q < 4; ++q) s = fmaf(x[q], x[q], s);
        #pragma unroll
        for (int off = 16; off > 0; off >>= 1) s += __shfl_xor_sync(0xffffffffu, s, off);
        float xn2 = fmaxf(sqrtf(s), 1e-5f);

        const float sqrt_c = 0.31622776601683794f;   // sqrt(0.1)
        float arg = sqrt_c * xn2;
        float es  = tanhf(arg) / arg;                // expmap0 scale
        #pragma unroll
        for (int q = 0; q < 4; ++q) x[q] *= es;

        s = 0.0f;
        #pragma unroll
        for (int q = 0; q < 4; ++q) s = fmaf(x[q], x[q], s);
        #pragma unroll
        for (int off = 16; off > 0; off >>= 1) s += __shfl_xor_sync(0xffffffffu, s, off);
        float n3 = fmaxf(sqrtf(s), 1e-5f);
        const float maxn = (1.0f - 1e-3f) / 0.31622776601683794f;
        if (n3 > maxn) {
            float ps = maxn / n3;
            #pragma unroll
            for (int q = 0; q < 4; ++q) x[q] *= ps;
            s *= ps * ps;
        }

        #pragma unroll
        for (int q = 0; q < 4; ++q) {
            g_lh[r * DIM + lane + 32 * q]   = x[q];
            g_lhT[(lane + 32 * q) * NP + r] = x[q];
        }
        if (lane == 0) g_y2[r] = s;

        __syncthreads();
        __threadfence();
        if (tid == 0) atomicAdd(&g_done, 1);
    }

    // ---- barrier: wait for all 32 producer blocks ----
    if (tid == 0) {
        while (*((volatile int*)&g_done) < 32) { }
    }
    __syncthreads();
    __threadfence();   // acquire: make produced lh/lhT/y2 visible

    // ---- dist phase ----
    __shared__ float xs[8 * DIM];
    __shared__ float sx2[8];

    const float* __restrict__ X;
    float* __restrict__ out;
    int r0;
    if (b < 128)      { X = z;    out = g_Dz;  r0 = b * 8; }
    else if (b < 256) { X = t;    out = g_Dt;  r0 = (b - 128) * 8; }
    else              { X = g_lh; out = g_Dll; r0 = (b - 256) * 8; }

    #pragma unroll
    for (int idx = tid; idx < 8 * DIM; idx += 256)
        xs[idx] = X[r0 * DIM + idx];
    __syncthreads();

    {
        float s = 0.0f;
        #pragma unroll
        for (int q = 0; q < 4; ++q) {
            float e = xs[warp * DIM + lane + 32 * q];
            s = fmaf(e, e, s);
        }
        #pragma unroll
        for (int off = 16; off > 0; off >>= 1)
            s += __shfl_down_sync(0xffffffffu, s, off);
        if (lane == 0) sx2[warp] = s;
    }
    __syncthreads();

    const int col = tid;
    float acc[8] = {0,0,0,0,0,0,0,0};
    #pragma unroll 4
    for (int d = 0; d < DIM; ++d) {
        float yv = g_lhT[d * NP + col];
        #pragma unroll
        for (int r = 0; r < 8; ++r)
            acc[r] = fmaf(xs[r * DIM + d], yv, acc[r]);
    }

    const float y2 = g_y2[col];
    const float c  = 0.1f;
    #pragma unroll
    for (int r = 0; r < 8; ++r) {
        float x2    = sx2[r];
        float xy    = -acc[r];                               // (-x).y
        float a     = 1.0f + 2.0f * c * xy + c * y2;
        float bb    = 1.0f - c * x2;
        float denom = 1.0f + 2.0f * c * xy + (c * c) * x2 * y2;
        float numsq = a * a * x2 + 2.0f * a * bb * xy + bb * bb * y2;
        float nrm   = sqrtf(fmaxf(numsq, 1e-12f)) / fabsf(denom + 1e-5f);
        float v = 0.31622776601683794f * nrm;
        v = fminf(fmaxf(v, -0.99999f), 0.99999f);
        float art = 0.5f * (log1pf(v) - log1pf(-v));
        out[(r0 + r) * NP + col] = 6.324555320336759f * art;
    }
}

// ---------------- fused ghhc over all 4 triplet sets -------------------------
// One warp per triplet; lane owns 8 contiguous proxies. Phase-split (no spill).
// Gumbel loads use __ldcs (evict-first). One fire-and-forget atomic per block.
// Also resets g_done for the next graph replay (runs strictly after dist).
__global__ __launch_bounds__(256, 4) void k_ghhc_all(
    const int*  __restrict__ t1, const int*  __restrict__ t2,
    const int*  __restrict__ t3, const int*  __restrict__ t4,
    const float* __restrict__ G1, const float* __restrict__ G2,
    const float* __restrict__ G3, const float* __restrict__ G4,
    float* __restrict__ outp) {
    __shared__ float wsum[8];
    const int warp = threadIdx.x >> 5;
    const int lane = threadIdx.x & 31;
    const int w    = blockIdx.x * 8 + warp;

    if (blockIdx.x == 0 && threadIdx.x == 0) g_done = 0;   // reset for next run

    const int* trip; const float* g; const float* D; int T, t; float invT;
    if (w < TB)                { trip = t1; g = G1; D = g_Dz;  T = TB; t = w;                 invT = 1.0f / TB; }
    else if (w < TB + TL)      { trip = t2; g = G2; D = g_Dll; T = TL; t = w - TB;            invT = 1.0f / TL; }
    else if (w < 2*TB + TL)    { trip = t3; g = G3; D = g_Dt;  T = TB; t = w - (TB + TL);     invT = 1.0f / TB; }
    else                       { trip = t4; g = G4; D = g_Dll; T = TL; t = w - (2*TB + TL);   invT = 1.0f / TL; }

    const int i = trip[t];
    const int j = trip[T + t];
    const int k = trip[2 * T + t];
    const float* __restrict__ di = D + (size_t)i * NP;
    const float* __restrict__ dj = D + (size_t)j * NP;
    const float* __restrict__ dk = D + (size_t)k * NP;
    const float* __restrict__ g0 = g + (size_t)t * NP;
    const float* __restrict__ g1 = g + ((size_t)T + t) * NP;
    const int base = lane * 8;

    float m[8];
    float best0 = -INFINITY, best1 = -INFINITY;
    int   idx0 = 0, idx1 = 0;

    // ---- phase A: di, dj, g0 -> max_ij, score0 ----
    {
        float4 a0 = *(const float4*)(di + base), a1 = *(const float4*)(di + base + 4);
        float4 b0 = *(const float4*)(dj + base), b1 = *(const float4*)(dj + base + 4);
        float4 e0 = __ldcs((const float4*)(g0 + base));
        float4 e1 = __ldcs((const float4*)(g0 + base + 4));
        float av[8] = {a0.x, a0.y, a0.z, a0.w, a1.x, a1.y, a1.z, a1.w};
        float bv[8] = {b0.x, b0.y, b0.z, b0.w, b1.x, b1.y, b1.z, b1.w};
        float ev[8] = {e0.x, e0.y, e0.z, e0.w, e1.x, e1.y, e1.z, e1.w};
        #pragma unroll
        for (int u = 0; u < 8; ++u) {
            m[u] = fmaxf(av[u], bv[u]);
            float s0 = fmaf(m[u], -10.0f, ev[u]);     // g - max/tau
            if (s0 > best0) { best0 = s0; idx0 = base + u; }
        }
    }
    // ---- phase B: dk, g1 -> max_ijk, score1 ----
    {
        float4 c0 = *(const float4*)(dk + base), c1 = *(const float4*)(dk + base + 4);
        float4 f0 = __ldcs((const float4*)(g1 + base));
        float4 f1 = __ldcs((const float4*)(g1 + base + 4));
        float cv[8] = {c0.x, c0.y, c0.z, c0.w, c1.x, c1.y, c1.z, c1.w};
        float fv[8] = {f0.x, f0.y, f0.z, f0.w, f1.x, f1.y, f1.z, f1.w};
        #pragma unroll
        for (int u = 0; u < 8; ++u) {
            float m2 = fmaxf(cv[u], m[u]);
            float s1 = fmaf(m2, -10.0f, fv[u]);
            if (s1 > best1) { best1 = s1; idx1 = base + u; }
        }
    }

    // warp argmax reduce, first-occurrence (lowest index) wins ties
    #pragma unroll
    for (int off = 16; off > 0; off >>= 1) {
        float ov = __shfl_down_sync(0xffffffffu, best0, off);
        int   oi = __shfl_down_sync(0xffffffffu, idx0,  off);
        if (ov > best0 || (ov == best0 && oi < idx0)) { best0 = ov; idx0 = oi; }
        float ow = __shfl_down_sync(0xffffffffu, best1, off);
        int   oj = __shfl_down_sync(0xffffffffu, idx1,  off);
        if (ow > best1 || (ow == best1 && oj < idx1)) { best1 = ow; idx1 = oj; }
    }

    float hc = 0.0f;
    if (lane == 0 && idx0 != idx1) {                  // diff_lca gate
        float dia = di[idx0], dib = di[idx1];
        float dja = dj[idx0], djb = dj[idx1];
        float dka = dk[idx0], dkb = dk[idx1];
        float h = fmaxf(dia - dib + 0.1f, 0.0f)
                + fmaxf(dja - djb + 0.1f, 0.0f)
                + fmaxf(dkb - dka + 0.1f, 0.0f);
        hc = h * invT;
    }
    if (lane == 0) wsum[warp] = hc;
    __syncthreads();

    if (threadIdx.x == 0) {
        float s = 0.0f;
        #pragma unroll
        for (int q = 0; q < 8; ++q) s += wsum[q];
        atomicAdd(outp, s);                           // fire-and-forget
    }
}

// ---------------- launch -----------------------------------------------------
extern "C" void kernel_launch(void* const* d_in, const int* in_sizes, int n_in,
                              void* d_out, int out_size) {
    const float* z_s   = (const float*)d_in[0];
    const float* t_s   = (const float*)d_in[1];
    /* d_in[2] = y, unused */
    const float* lcas  = (const float*)d_in[3];
    const int*   trip1 = (const int*)d_in[4];
    const int*   trip2 = (const int*)d_in[5];
    const int*   trip3 = (const int*)d_in[6];
    const int*   trip4 = (const int*)d_in[7];
    const float* g1    = (const float*)d_in[8];
    const float* g2    = (const float*)d_in[9];
    const float* g3    = (const float*)d_in[10];
    const float* g4    = (const float*)d_in[11];

    k_dist_all<<<288, 256>>>(lcas, z_s, t_s, (float*)d_out);
    k_ghhc_all<<<NGBLK, 256>>>(trip1, trip2, trip3, trip4,
                               g1, g2, g3, g4, (float*)d_out);
}

// round 8
// speedup vs baseline: 1.1805x; 1.1805x over previous
#include <cuda_runtime.h>
#include <math.h>
#include <stdint.h>

#define BSZ   1024
#define NP    256
#define DIM   128
#define TB    51200      // triplets per batch segment (T1 == T3)
#define TL    12800      // triplets per lca segment   (T2 == T4)
#define TTOT  (2*TB + 2*TL)
#define NGBLK (TTOT / 8)

// ---------------- scratch (static device globals; no allocation) ------------
__device__ float  g_lh[NP * DIM];    // poincare-mapped lcas, row-major
__device__ float  g_lhT[DIM * NP];   // transposed for coalesced dist loads
__device__ float  g_y2[NP];          // ||lh||^2 per proxy
__device__ float  g_Dz[BSZ * NP];    // dist(z_s, lh)
__device__ float  g_Dt[BSZ * NP];    // dist(t_s, lh)
__device__ float  g_Dll[NP * NP];    // dist(lh, lh)

// monotone float->u32 map: preserves ordering for all finite floats
__device__ __forceinline__ unsigned ordu(float f) {
    int b = __float_as_int(f);
    return (unsigned)(b ^ ((b >> 31) | 0x80000000));
}

// ---------------- to_poincare: warp per row, shuffle reductions --------------
__global__ __launch_bounds__(256) void k_poincare(const float* __restrict__ lcas,
                                                  float* __restrict__ outp) {
    const int warp = threadIdx.x >> 5;
    const int lane = threadIdx.x & 31;
    const int r    = blockIdx.x * 8 + warp;
    if (blockIdx.x == 0 && threadIdx.x == 0) outp[0] = 0.0f;

    float x[4];
    #pragma unroll
    for (int q = 0; q < 4; ++q) x[q] = lcas[r * DIM + lane + 32 * q];

    float s = 0.0f;
    #pragma unroll
    for (int q = 0; q < 4; ++q) s = fmaf(x[q], x[q], s);
    #pragma unroll
    for (int off = 16; off > 0; off >>= 1) s += __shfl_xor_sync(0xffffffffu, s, off);
    float xn = sqrtf(s) + 1e-5f;

    float scale = fminf(1.0f, 2.3f / xn);
    #pragma unroll
    for (int q = 0; q < 4; ++q) x[q] *= scale;

    s = 0.0f;
    #pragma unroll
    for (int q = 0; q < 4; ++q) s = fmaf(x[q], x[q], s);
    #pragma unroll
    for (int off = 16; off > 0; off >>= 1) s += __shfl_xor_sync(0xffffffffu, s, off);
    float xn2 = fmaxf(sqrtf(s), 1e-5f);

    const float sqrt_c = 0.31622776601683794f;   // sqrt(0.1)
    float arg = sqrt_c * xn2;
    float es  = tanhf(arg) / arg;                // expmap0 scale
    #pragma unroll
    for (int q = 0; q < 4; ++q) x[q] *= es;

    s = 0.0f;
    #pragma unroll
    for (int q = 0; q < 4; ++q) s = fmaf(x[q], x[q], s);
    #pragma unroll
    for (int off = 16; off > 0; off >>= 1) s += __shfl_xor_sync(0xffffffffu, s, off);
    float n3 = fmaxf(sqrtf(s), 1e-5f);
    const float maxn = (1.0f - 1e-3f) / 0.31622776601683794f;
    if (n3 > maxn) {
        float ps = maxn / n3;
        #pragma unroll
        for (int q = 0; q < 4; ++q) x[q] *= ps;
        s *= ps * ps;
    }

    #pragma unroll
    for (int q = 0; q < 4; ++q) {
        g_lh[r * DIM + lane + 32 * q]   = x[q];
        g_lhT[(lane + 32 * q) * NP + r] = x[q];
    }
    if (lane == 0) g_y2[r] = s;
}

// ---------------- fused distance matrices -----------------------------------
__global__ __launch_bounds__(256) void k_dist_all(const float* __restrict__ z,
                                                  const float* __restrict__ t) {
    __shared__ float xs[8 * DIM];
    __shared__ float sx2[8];
    const int b   = blockIdx.x;
    const int tid = threadIdx.x;

    const float* __restrict__ X;
    float* __restrict__ out;
    int r0;
    if (b < 128)      { X = z;    out = g_Dz;  r0 = b * 8; }
    else if (b < 256) { X = t;    out = g_Dt;  r0 = (b - 128) * 8; }
    else              { X = g_lh; out = g_Dll; r0 = (b - 256) * 8; }

    #pragma unroll
    for (int idx = tid; idx < 8 * DIM; idx += 256)
        xs[idx] = X[r0 * DIM + idx];
    __syncthreads();

    const int warp = tid >> 5, lane = tid & 31;
    {
        float s = 0.0f;
        #pragma unroll
        for (int q = 0; q < 4; ++q) {
            float e = xs[warp * DIM + lane + 32 * q];
            s = fmaf(e, e, s);
        }
        #pragma unroll
        for (int off = 16; off > 0; off >>= 1)
            s += __shfl_down_sync(0xffffffffu, s, off);
        if (lane == 0) sx2[warp] = s;
    }
    __syncthreads();

    const int col = tid;
    float acc[8] = {0,0,0,0,0,0,0,0};
    #pragma unroll 4
    for (int d = 0; d < DIM; ++d) {
        float yv = g_lhT[d * NP + col];
        #pragma unroll
        for (int r = 0; r < 8; ++r)
            acc[r] = fmaf(xs[r * DIM + d], yv, acc[r]);
    }

    const float y2 = g_y2[col];
    const float c  = 0.1f;
    #pragma unroll
    for (int r = 0; r < 8; ++r) {
        float x2    = sx2[r];
        float xy    = -acc[r];                               // (-x).y
        float a     = 1.0f + 2.0f * c * xy + c * y2;
        float bb    = 1.0f - c * x2;
        float denom = 1.0f + 2.0f * c * xy + (c * c) * x2 * y2;
        float numsq = a * a * x2 + 2.0f * a * bb * xy + bb * bb * y2;
        float nrm   = sqrtf(fmaxf(numsq, 1e-12f)) / fabsf(denom + 1e-5f);
        float v = 0.31622776601683794f * nrm;
        v = fminf(fmaxf(v, -0.99999f), 0.99999f);
        float art = 0.5f * (log1pf(v) - log1pf(-v));
        out[(r0 + r) * NP + col] = 6.324555320336759f * art;
    }
}

// ---------------- fused ghhc over all 4 triplet sets -------------------------
// One warp per triplet; lane owns 8 contiguous proxies. Phase-split (no spill).
// Argmax via orderable-u32 + REDUX.MAX + ballot (replaces shuffle-tree + per-
// element index selects). Gumbel via __ldcs. One atomic per block.
__global__ __launch_bounds__(256, 5) void k_ghhc_all(
    const int*  __restrict__ t1, const int*  __restrict__ t2,
    const int*  __restrict__ t3, const int*  __restrict__ t4,
    const float* __restrict__ G1, const float* __restrict__ G2,
    const float* __restrict__ G3, const float* __restrict__ G4,
    float* __restrict__ outp) {
    __shared__ float wsum[8];
    const int warp = threadIdx.x >> 5;
    const int lane = threadIdx.x & 31;
    const int w    = blockIdx.x * 8 + warp;

    const int* trip; const float* g; const float* D; int T, t; float invT;
    if (w < TB)                { trip = t1; g = G1; D = g_Dz;  T = TB; t = w;                 invT = 1.0f / TB; }
    else if (w < TB + TL)      { trip = t2; g = G2; D = g_Dll; T = TL; t = w - TB;            invT = 1.0f / TL; }
    else if (w < 2*TB + TL)    { trip = t3; g = G3; D = g_Dt;  T = TB; t = w - (TB + TL);     invT = 1.0f / TB; }
    else                       { trip = t4; g = G4; D = g_Dll; T = TL; t = w - (2*TB + TL);   invT = 1.0f / TL; }

    const int i = trip[t];
    const int j = trip[T + t];
    const int k = trip[2 * T + t];
    const float* __restrict__ di = D + (size_t)i * NP;
    const float* __restrict__ dj = D + (size_t)j * NP;
    const float* __restrict__ dk = D + (size_t)k * NP;
    const float* __restrict__ g0 = g + (size_t)t * NP;
    const float* __restrict__ g1 = g + ((size_t)T + t) * NP;
    const int base = lane * 8;

    float m[8];
    int idx0, idx1;

    // ---- phase A: di, dj, g0 -> max_ij, argmax0 ----
    {
        float4 a0 = *(const float4*)(di + base), a1 = *(const float4*)(di + base + 4);
        float4 b0 = *(const float4*)(dj + base), b1 = *(const float4*)(dj + base + 4);
        float4 e0 = __ldcs((const float4*)(g0 + base));
        float4 e1 = __ldcs((const float4*)(g0 + base + 4));
        float av[8] = {a0.x, a0.y, a0.z, a0.w, a1.x, a1.y, a1.z, a1.w};
        float bv[8] = {b0.x, b0.y, b0.z, b0.w, b1.x, b1.y, b1.z, b1.w};
        float ev[8] = {e0.x, e0.y, e0.z, e0.w, e1.x, e1.y, e1.z, e1.w};
        unsigned tu[8], bmax = 0u;
        #pragma unroll
        for (int u = 0; u < 8; ++u) {
            m[u]  = fmaxf(av[u], bv[u]);
            tu[u] = ordu(fmaf(m[u], -10.0f, ev[u]));  // ord(g - max/tau)
            bmax  = max(bmax, tu[u]);
        }
        bmax = __reduce_max_sync(0xffffffffu, bmax);
        int loc = NP;                                 // sentinel
        #pragma unroll
        for (int u = 7; u >= 0; --u)
            if (tu[u] == bmax) loc = base + u;        // lowest u wins
        unsigned msk = __ballot_sync(0xffffffffu, loc < NP);
        idx0 = __shfl_sync(0xffffffffu, loc, __ffs(msk) - 1);
    }
    // ---- phase B: dk, g1 -> max_ijk, argmax1 ----
    {
        float4 c0 = *(const float4*)(dk + base), c1 = *(const float4*)(dk + base + 4);
        float4 f0 = __ldcs((const float4*)(g1 + base));
        float4 f1 = __ldcs((const float4*)(g1 + base + 4));
        float cv[8] = {c0.x, c0.y, c0.z, c0.w, c1.x, c1.y, c1.z, c1.w};
        float fv[8] = {f0.x, f0.y, f0.z, f0.w, f1.x, f1.y, f1.z, f1.w};
        unsigned tu[8], bmax = 0u;
        #pragma unroll
        for (int u = 0; u < 8; ++u) {
            float m2 = fmaxf(cv[u], m[u]);
            tu[u] = ordu(fmaf(m2, -10.0f, fv[u]));
            bmax  = max(bmax, tu[u]);
        }
        bmax = __reduce_max_sync(0xffffffffu, bmax);
        int loc = NP;
        #pragma unroll
        for (int u = 7; u >= 0; --u)
            if (tu[u] == bmax) loc = base + u;
        unsigned msk = __ballot_sync(0xffffffffu, loc < NP);
        idx1 = __shfl_sync(0xffffffffu, loc, __ffs(msk) - 1);
    }

    float hc = 0.0f;
    if (lane == 0 && idx0 != idx1) {                  // diff_lca gate
        float dia = di[idx0], dib = di[idx1];
        float dja = dj[idx0], djb = dj[idx1];
        float dka = dk[idx0], dkb = dk[idx1];
        float h = fmaxf(dia - dib + 0.1f, 0.0f)
                + fmaxf(dja - djb + 0.1f, 0.0f)
                + fmaxf(dkb - dka + 0.1f, 0.0f);
        hc = h * invT;
    }
    if (lane == 0) wsum[warp] = hc;
    __syncthreads();

    if (threadIdx.x == 0) {
        float s = 0.0f;
        #pragma unroll
        for (int q = 0; q < 8; ++q) s += wsum[q];
        atomicAdd(outp, s);                           // fire-and-forget
    }
}

// ---------------- launch -----------------------------------------------------
extern "C" void kernel_launch(void* const* d_in, const int* in_sizes, int n_in,
                              void* d_out, int out_size) {
    const float* z_s   = (const float*)d_in[0];
    const float* t_s   = (const float*)d_in[1];
    /* d_in[2] = y, unused */
    const float* lcas  = (const float*)d_in[3];
    const int*   trip1 = (const int*)d_in[4];
    const int*   trip2 = (const int*)d_in[5];
    const int*   trip3 = (const int*)d_in[6];
    const int*   trip4 = (const int*)d_in[7];
    const float* g1    = (const float*)d_in[8];
    const float* g2    = (const float*)d_in[9];
    const float* g3    = (const float*)d_in[10];
    const float* g4    = (const float*)d_in[11];

    k_poincare<<<32, 256>>>(lcas, (float*)d_out);
    k_dist_all<<<288, 256>>>(z_s, t_s);
    k_ghhc_all<<<NGBLK, 256>>>(trip1, trip2, trip3, trip4,
                               g1, g2, g3, g4, (float*)d_out);
}

// round 9
// speedup vs baseline: 1.2125x; 1.0270x over previous
#include <cuda_runtime.h>
#include <math.h>
#include <stdint.h>

#define BSZ   1024
#define NP    256
#define DIM   128
#define TB    51200      // triplets per batch segment (T1 == T3)
#define TL    12800      // triplets per lca segment   (T2 == T4)
#define TTOT  (2*TB + 2*TL)
#define NGBLK (TTOT / 8)
#define LPAD  129        // smem row stride (conflict-free for c-consecutive access)

// ---------------- scratch (static device globals; no allocation) ------------
__device__ float  g_Dz[BSZ * NP];    // dist(z_s, lh)
__device__ float  g_Dt[BSZ * NP];    // dist(t_s, lh)
__device__ float  g_Dll[NP * NP];    // dist(lh, lh)

// monotone float->u32 map: preserves ordering for all finite floats
__device__ __forceinline__ unsigned ordu(float f) {
    int b = __float_as_int(f);
    return (unsigned)(b ^ ((b >> 31) | 0x80000000));
}

// poincare composite scale + final squared norm, from the raw row norm n0
__device__ __forceinline__ void poinc_scales(float sum0, float& alpha, float& y2) {
    const float sqrt_c = 0.31622776601683794f;       // sqrt(0.1)
    const float maxn   = (1.0f - 1e-3f) / 0.31622776601683794f;
    float n0 = sqrtf(sum0);
    float s1 = fminf(1.0f, 2.3f / (n0 + 1e-5f));     // clip to radius 2.3
    float n1 = fmaxf(n0 * s1, 1e-5f);
    float arg = sqrt_c * n1;
    float s2 = tanhf(arg) / arg;                     // expmap0
    float n2 = fmaxf(n1 * s2, 1e-5f);
    float s3 = (n2 > maxn) ? (maxn / n2) : 1.0f;     // project
    float n3 = n2 * s3;
    alpha = s1 * s2 * s3;
    y2    = n3 * n3;
}

// ---------------- self-contained distance matrices ---------------------------
// Fuses to_poincare into the dist kernel: lh = alpha ⊙ lcas (per-row scalar),
// so each block tiles 64 raw lcas rows (the D columns) into smem, computes the
// 64 alphas in-block, scales the tile, and does an all-smem GEMM-ish dot.
// grid 288 = 72 row-segments (32 z-blk, 32 t-blk, 8 lh-blk of 32 rows) x 4 col tiles.
__global__ __launch_bounds__(256) void k_dist_all(const float* __restrict__ lcas,
                                                  const float* __restrict__ z,
                                                  const float* __restrict__ t,
                                                  float* __restrict__ outp) {
    __shared__ float ls[64 * LPAD];   // column tile: 64 lcas rows (scaled to lh)
    __shared__ float xs[32 * LPAD];   // X tile: 32 source rows
    __shared__ float y2c[64];         // ||lh_col||^2
    __shared__ float x2r[32];         // ||x_row||^2 (post-scale for lh rows)

    const int b    = blockIdx.x;
    const int tid  = threadIdx.x;
    const int warp = tid >> 5, lane = tid & 31;

    if (b == 0 && tid == 0) outp[0] = 0.0f;          // zero loss accumulator

    const int ct = b & 3;            // column tile 0..3
    const int rb = b >> 2;           // row segment 0..71
    const int c0 = ct * 64;

    const float* __restrict__ X;
    float* __restrict__ out;
    int r0; bool x_is_lh;
    if (rb < 32)      { X = z;    out = g_Dz;  r0 = rb * 32;        x_is_lh = false; }
    else if (rb < 64) { X = t;    out = g_Dt;  r0 = (rb - 32) * 32; x_is_lh = false; }
    else              { X = lcas; out = g_Dll; r0 = (rb - 64) * 32; x_is_lh = true;  }

    // ---- load tiles (coalesced global reads) ----
    #pragma unroll
    for (int idx = tid; idx < 64 * DIM; idx += 256) {
        int r = idx >> 7, d = idx & 127;
        ls[r * LPAD + d] = lcas[(c0 + r) * DIM + d];
    }
    #pragma unroll
    for (int idx = tid; idx < 32 * DIM; idx += 256) {
        int r = idx >> 7, d = idx & 127;
        xs[r * LPAD + d] = X[(r0 + r) * DIM + d];
    }
    __syncthreads();

    // ---- poincare-scale the column tile: warp w handles cols w*8..w*8+7 ----
    #pragma unroll
    for (int cc = 0; cc < 8; ++cc) {
        const int col = warp * 8 + cc;
        float v[4], s = 0.0f;
        #pragma unroll
        for (int q = 0; q < 4; ++q) {
            v[q] = ls[col * LPAD + lane + 32 * q];
            s = fmaf(v[q], v[q], s);
        }
        #pragma unroll
        for (int off = 16; off > 0; off >>= 1) s += __shfl_xor_sync(0xffffffffu, s, off);
        float alpha, y2; poinc_scales(s, alpha, y2);
        #pragma unroll
        for (int q = 0; q < 4; ++q) ls[col * LPAD + lane + 32 * q] = v[q] * alpha;
        if (lane == 0) y2c[col] = y2;
    }
    // ---- X rows: warp w handles rows w*4..w*4+3 ----
    #pragma unroll
    for (int rr = 0; rr < 4; ++rr) {
        const int row = warp * 4 + rr;
        float v[4], s = 0.0f;
        #pragma unroll
        for (int q = 0; q < 4; ++q) {
            v[q] = xs[row * LPAD + lane + 32 * q];
            s = fmaf(v[q], v[q], s);
        }
        #pragma unroll
        for (int off = 16; off > 0; off >>= 1) s += __shfl_xor_sync(0xffffffffu, s, off);
        if (x_is_lh) {
            float alpha, y2; poinc_scales(s, alpha, y2);
            #pragma unroll
            for (int q = 0; q < 4; ++q) xs[row * LPAD + lane + 32 * q] = v[q] * alpha;
            if (lane == 0) x2r[row] = y2;
        } else {
            if (lane == 0) x2r[row] = s;
        }
    }
    __syncthreads();

    // ---- dot products: thread = (col c = tid&63, row group rg = tid>>6) ----
    const int c  = tid & 63;
    const int rg = tid >> 6;          // 0..3, 8 rows each
    float acc[8] = {0,0,0,0,0,0,0,0};
    #pragma unroll 4
    for (int d = 0; d < DIM; ++d) {
        float lv = ls[c * LPAD + d];  // conflict-free: (c+d)%32 distinct in warp
        #pragma unroll
        for (int q = 0; q < 8; ++q)
            acc[q] = fmaf(xs[(rg * 8 + q) * LPAD + d], lv, acc[q]);
    }

    // ---- hyperbolic distance epilogue + store ----
    const float y2 = y2c[c];
    const float cc_ = 0.1f;
    #pragma unroll
    for (int q = 0; q < 8; ++q) {
        const int row = rg * 8 + q;
        float x2    = x2r[row];
        float xy    = -acc[q];                               // (-x).y
        float a     = 1.0f + 2.0f * cc_ * xy + cc_ * y2;
        float bb    = 1.0f - cc_ * x2;
        float denom = 1.0f + 2.0f * cc_ * xy + (cc_ * cc_) * x2 * y2;
        float numsq = a * a * x2 + 2.0f * a * bb * xy + bb * bb * y2;
        float nrm   = sqrtf(fmaxf(numsq, 1e-12f)) / fabsf(denom + 1e-5f);
        float v = 0.31622776601683794f * nrm;
        v = fminf(fmaxf(v, -0.99999f), 0.99999f);
        float art = 0.5f * (log1pf(v) - log1pf(-v));
        out[(r0 + row) * NP + (c0 + c)] = 6.324555320336759f * art;
    }
}

// ---------------- fused ghhc over all 4 triplet sets -------------------------
// One warp per triplet; lane owns 8 contiguous proxies. Phase-split (no spill).
// Argmax via orderable-u32 + REDUX.MAX + ballot. Gumbel via __ldcs.
__global__ __launch_bounds__(256, 5) void k_ghhc_all(
    const int*  __restrict__ t1, const int*  __restrict__ t2,
    const int*  __restrict__ t3, const int*  __restrict__ t4,
    const float* __restrict__ G1, const float* __restrict__ G2,
    const float* __restrict__ G3, const float* __restrict__ G4,
    float* __restrict__ outp) {
    __shared__ float wsum[8];
    const int warp = threadIdx.x >> 5;
    const int lane = threadIdx.x & 31;
    const int w    = blockIdx.x * 8 + warp;

    const int* trip; const float* g; const float* D; int T, t; float invT;
    if (w < TB)                { trip = t1; g = G1; D = g_Dz;  T = TB; t = w;                 invT = 1.0f / TB; }
    else if (w < TB + TL)      { trip = t2; g = G2; D = g_Dll; T = TL; t = w - TB;            invT = 1.0f / TL; }
    else if (w < 2*TB + TL)    { trip = t3; g = G3; D = g_Dt;  T = TB; t = w - (TB + TL);     invT = 1.0f / TB; }
    else                       { trip = t4; g = G4; D = g_Dll; T = TL; t = w - (2*TB + TL);   invT = 1.0f / TL; }

    const int i = trip[t];
    const int j = trip[T + t];
    const int k = trip[2 * T + t];
    const float* __restrict__ di = D + (size_t)i * NP;
    const float* __restrict__ dj = D + (size_t)j * NP;
    const float* __restrict__ dk = D + (size_t)k * NP;
    const float* __restrict__ g0 = g + (size_t)t * NP;
    const float* __restrict__ g1 = g + ((size_t)T + t) * NP;
    const int base = lane * 8;

    float m[8];
    int idx0, idx1;

    // ---- phase A: di, dj, g0 -> max_ij, argmax0 ----
    {
        float4 a0 = *(const float4*)(di + base), a1 = *(const float4*)(di + base + 4);
        float4 b0 = *(const float4*)(dj + base), b1 = *(const float4*)(dj + base + 4);
        float4 e0 = __ldcs((const float4*)(g0 + base));
        float4 e1 = __ldcs((const float4*)(g0 + base + 4));
        float av[8] = {a0.x, a0.y, a0.z, a0.w, a1.x, a1.y, a1.z, a1.w};
        float bv[8] = {b0.x, b0.y, b0.z, b0.w, b1.x, b1.y, b1.z, b1.w};
        float ev[8] = {e0.x, e0.y, e0.z, e0.w, e1.x, e1.y, e1.z, e1.w};
        unsigned tu[8], bmax = 0u;
        #pragma unroll
        for (int u = 0; u < 8; ++u) {
            m[u]  = fmaxf(av[u], bv[u]);
            tu[u] = ordu(fmaf(m[u], -10.0f, ev[u]));  // ord(g - max/tau)
            bmax  = max(bmax, tu[u]);
        }
        bmax = __reduce_max_sync(0xffffffffu, bmax);
        int loc = NP;                                 // sentinel
        #pragma unroll
        for (int u = 7; u >= 0; --u)
            if (tu[u] == bmax) loc = base + u;        // lowest u wins
        unsigned msk = __ballot_sync(0xffffffffu, loc < NP);
        idx0 = __shfl_sync(0xffffffffu, loc, __ffs(msk) - 1);
    }
    // ---- phase B: dk, g1 -> max_ijk, argmax1 ----
    {
        float4 c0 = *(const float4*)(dk + base), c1 = *(const float4*)(dk + base + 4);
        float4 f0 = __ldcs((const float4*)(g1 + base));
        float4 f1 = __ldcs((const float4*)(g1 + base + 4));
        float cv[8] = {c0.x, c0.y, c0.z, c0.w, c1.x, c1.y, c1.z, c1.w};
        float fv[8] = {f0.x, f0.y, f0.z, f0.w, f1.x, f1.y, f1.z, f1.w};
        unsigned tu[8], bmax = 0u;
        #pragma unroll
        for (int u = 0; u < 8; ++u) {
            float m2 = fmaxf(cv[u], m[u]);
            tu[u] = ordu(fmaf(m2, -10.0f, fv[u]));
            bmax  = max(bmax, tu[u]);
        }
        bmax = __reduce_max_sync(0xffffffffu, bmax);
        int loc = NP;
        #pragma unroll
        for (int u = 7; u >= 0; --u)
            if (tu[u] == bmax) loc = base + u;
        unsigned msk = __ballot_sync(0xffffffffu, loc < NP);
        idx1 = __shfl_sync(0xffffffffu, loc, __ffs(msk) - 1);
    }

    float hc = 0.0f;
    if (lane == 0 && idx0 != idx1) {                  // diff_lca gate
        float dia = di[idx0], dib = di[idx1];
        float dja = dj[idx0], djb = dj[idx1];
        float dka = dk[idx0], dkb = dk[idx1];
        float h = fmaxf(dia - dib + 0.1f, 0.0f)
                + fmaxf(dja - djb + 0.1f, 0.0f)
                + fmaxf(dkb - dka + 0.1f, 0.0f);
        hc = h * invT;
    }
    if (lane == 0) wsum[warp] = hc;
    __syncthreads();

    if (threadIdx.x == 0) {
        float s = 0.0f;
        #pragma unroll
        for (int q = 0; q < 8; ++q) s += wsum[q];
        atomicAdd(outp, s);                           // fire-and-forget
    }
}

// ---------------- launch -----------------------------------------------------
extern "C" void kernel_launch(void* const* d_in, const int* in_sizes, int n_in,
                              void* d_out, int out_size) {
    const float* z_s   = (const float*)d_in[0];
    const float* t_s   = (const float*)d_in[1];
    /* d_in[2] = y, unused */
    const float* lcas  = (const float*)d_in[3];
    const int*   trip1 = (const int*)d_in[4];
    const int*   trip2 = (const int*)d_in[5];
    const int*   trip3 = (const int*)d_in[6];
    const int*   trip4 = (const int*)d_in[7];
    const float* g1    = (const float*)d_in[8];
    const float* g2    = (const float*)d_in[9];
    const float* g3    = (const float*)d_in[10];
    const float* g4    = (const float*)d_in[11];

    k_dist_all<<<288, 256>>>(lcas, z_s, t_s, (float*)d_out);
    k_ghhc_all<<<NGBLK, 256>>>(trip1, trip2, trip3, trip4,
                               g1, g2, g3, g4, (float*)d_out);
}

// round 11
// speedup vs baseline: 1.2400x; 1.0227x over previous
#include <cuda_runtime.h>
#include <math.h>
#include <stdint.h>

#define BSZ   1024
#define NP    256
#define DIM   128
#define TB    51200      // triplets per batch segment (T1 == T3)
#define TL    12800      // triplets per lca segment   (T2 == T4)
#define TTOT  (2*TB + 2*TL)
#define NGBLK (TTOT / 8)
#define LPAD  129        // smem row stride (conflict-free for c-consecutive access)

// ---------------- scratch (static device globals; no allocation) ------------
__device__ float  g_Dz[BSZ * NP];    // dist(z_s, lh)
__device__ float  g_Dt[BSZ * NP];    // dist(t_s, lh)
__device__ float  g_Dll[NP * NP];    // dist(lh, lh)

// monotone float->u32 map (order-preserving, injective) and its inverse
__device__ __forceinline__ unsigned ordu(float f) {
    int b = __float_as_int(f);
    return (unsigned)(b ^ ((b >> 31) | 0x80000000));
}
__device__ __forceinline__ float iordu(unsigned u) {
    unsigned b = (u & 0x80000000u) ? (u ^ 0x80000000u) : ~u;
    return __int_as_float((int)b);
}

// streaming 32B load: no L1 allocation, L2 evict-first (zero-reuse gumbel).
// sm_103 requires 256-bit width (.v4.b64) for this modifier combination.
__device__ __forceinline__ void ldg_stream8(const float* p, float* v) {
    unsigned long long q0, q1, q2, q3;
    asm("ld.global.L1::no_allocate.L2::evict_first.v4.b64 {%0,%1,%2,%3}, [%4];"
        : "=l"(q0), "=l"(q1), "=l"(q2), "=l"(q3) : "l"(p));
    v[0] = __uint_as_float((unsigned)q0);  v[1] = __uint_as_float((unsigned)(q0 >> 32));
    v[2] = __uint_as_float((unsigned)q1);  v[3] = __uint_as_float((unsigned)(q1 >> 32));
    v[4] = __uint_as_float((unsigned)q2);  v[5] = __uint_as_float((unsigned)(q2 >> 32));
    v[6] = __uint_as_float((unsigned)q3);  v[7] = __uint_as_float((unsigned)(q3 >> 32));
}

// poincare composite scale + final squared norm, from the raw row norm^2
__device__ __forceinline__ void poinc_scales(float sum0, float& alpha, float& y2) {
    const float sqrt_c = 0.31622776601683794f;       // sqrt(0.1)
    const float maxn   = (1.0f - 1e-3f) / 0.31622776601683794f;
    float n0 = sqrtf(sum0);
    float s1 = fminf(1.0f, 2.3f / (n0 + 1e-5f));     // clip to radius 2.3
    float n1 = fmaxf(n0 * s1, 1e-5f);
    float arg = sqrt_c * n1;
    float s2 = tanhf(arg) / arg;                     // expmap0
    float n2 = fmaxf(n1 * s2, 1e-5f);
    float s3 = (n2 > maxn) ? (maxn / n2) : 1.0f;     // project
    float n3 = n2 * s3;
    alpha = s1 * s2 * s3;
    y2    = n3 * n3;
}

// ---------------- self-contained distance matrices ---------------------------
// lh = alpha ⊙ lcas (per-row scalar), computed in-block from raw lcas tiles.
// grid 288 = 72 row-segments (32 z, 32 t, 8 lh of 32 rows) x 4 col tiles.
__global__ __launch_bounds__(256) void k_dist_all(const float* __restrict__ lcas,
                                                  const float* __restrict__ z,
                                                  const float* __restrict__ t,
                                                  float* __restrict__ outp) {
    __shared__ float ls[64 * LPAD];   // column tile: 64 lcas rows (scaled to lh)
    __shared__ float xs[32 * LPAD];   // X tile: 32 source rows
    __shared__ float y2c[64];         // ||lh_col||^2
    __shared__ float x2r[32];         // ||x_row||^2 (post-scale for lh rows)

    const int b    = blockIdx.x;
    const int tid  = threadIdx.x;
    const int warp = tid >> 5, lane = tid & 31;

    if (b == 0 && tid == 0) outp[0] = 0.0f;          // zero loss accumulator

    const int ct = b & 3;            // column tile 0..3
    const int rb = b >> 2;           // row segment 0..71
    const int c0 = ct * 64;

    const float* __restrict__ X;
    float* __restrict__ out;
    int r0; bool x_is_lh;
    if (rb < 32)      { X = z;    out = g_Dz;  r0 = rb * 32;        x_is_lh = false; }
    else if (rb < 64) { X = t;    out = g_Dt;  r0 = (rb - 32) * 32; x_is_lh = false; }
    else              { X = lcas; out = g_Dll; r0 = (rb - 64) * 32; x_is_lh = true;  }

    // ---- load tiles (coalesced global reads) ----
    #pragma unroll
    for (int idx = tid; idx < 64 * DIM; idx += 256) {
        int r = idx >> 7, d = idx & 127;
        ls[r * LPAD + d] = lcas[(c0 + r) * DIM + d];
    }
    #pragma unroll
    for (int idx = tid; idx < 32 * DIM; idx += 256) {
        int r = idx >> 7, d = idx & 127;
        xs[r * LPAD + d] = X[(r0 + r) * DIM + d];
    }
    __syncthreads();

    // ---- poincare-scale the column tile: warp w handles cols w*8..w*8+7 ----
    #pragma unroll
    for (int cc = 0; cc < 8; ++cc) {
        const int col = warp * 8 + cc;
        float v[4], s = 0.0f;
        #pragma unroll
        for (int q = 0; q < 4; ++q) {
            v[q] = ls[col * LPAD + lane + 32 * q];
            s = fmaf(v[q], v[q], s);
        }
        #pragma unroll
        for (int off = 16; off > 0; off >>= 1) s += __shfl_xor_sync(0xffffffffu, s, off);
        float alpha, y2; poinc_scales(s, alpha, y2);
        #pragma unroll
        for (int q = 0; q < 4; ++q) ls[col * LPAD + lane + 32 * q] = v[q] * alpha;
        if (lane == 0) y2c[col] = y2;
    }
    // ---- X rows: warp w handles rows w*4..w*4+3 ----
    #pragma unroll
    for (int rr = 0; rr < 4; ++rr) {
        const int row = warp * 4 + rr;
        float v[4], s = 0.0f;
        #pragma unroll
        for (int q = 0; q < 4; ++q) {
            v[q] = xs[row * LPAD + lane + 32 * q];
            s = fmaf(v[q], v[q], s);
        }
        #pragma unroll
        for (int off = 16; off > 0; off >>= 1) s += __shfl_xor_sync(0xffffffffu, s, off);
        if (x_is_lh) {
            float alpha, y2; poinc_scales(s, alpha, y2);
            #pragma unroll
            for (int q = 0; q < 4; ++q) xs[row * LPAD + lane + 32 * q] = v[q] * alpha;
            if (lane == 0) x2r[row] = y2;
        } else {
            if (lane == 0) x2r[row] = s;
        }
    }
    __syncthreads();

    // ---- dot products: thread = (col c = tid&63, row group rg = tid>>6) ----
    const int c  = tid & 63;
    const int rg = tid >> 6;          // 0..3, 8 rows each
    float acc[8] = {0,0,0,0,0,0,0,0};
    #pragma unroll 4
    for (int d = 0; d < DIM; ++d) {
        float lv = ls[c * LPAD + d];
        #pragma unroll
        for (int q = 0; q < 8; ++q)
            acc[q] = fmaf(xs[(rg * 8 + q) * LPAD + d], lv, acc[q]);
    }

    // ---- hyperbolic distance epilogue + store ----
    const float y2 = y2c[c];
    const float cc_ = 0.1f;
    #pragma unroll
    for (int q = 0; q < 8; ++q) {
        const int row = rg * 8 + q;
        float x2    = x2r[row];
        float xy    = -acc[q];                               // (-x).y
        float a     = 1.0f + 2.0f * cc_ * xy + cc_ * y2;
        float bb    = 1.0f - cc_ * x2;
        float denom = 1.0f + 2.0f * cc_ * xy + (cc_ * cc_) * x2 * y2;
        float numsq = a * a * x2 + 2.0f * a * bb * xy + bb * bb * y2;
        float nrm   = sqrtf(fmaxf(numsq, 1e-12f)) / fabsf(denom + 1e-5f);
        float v = 0.31622776601683794f * nrm;
        v = fminf(fmaxf(v, -0.99999f), 0.99999f);
        float art = 0.5f * (log1pf(v) - log1pf(-v));
        out[(r0 + row) * NP + (c0 + c)] = 6.324555320336759f * art;
    }
}

// ---------------- fused ghhc over all 4 triplet sets -------------------------
// One warp per triplet; lane owns 8 contiguous proxies. Phase-split (no spill).
// Max tracked in float (FMNMX, fma pipe); one ordu+REDUX.MAX.U32 per phase;
// index resolved by exact float-equality match + ballot. Gumbel loads are
// 256-bit streaming (no L1 fill, L2 evict-first).
__global__ __launch_bounds__(256, 5) void k_ghhc_all(
    const int*  __restrict__ t1, const int*  __restrict__ t2,
    const int*  __restrict__ t3, const int*  __restrict__ t4,
    const float* __restrict__ G1, const float* __restrict__ G2,
    const float* __restrict__ G3, const float* __restrict__ G4,
    float* __restrict__ outp) {
    __shared__ float wsum[8];
    const int warp = threadIdx.x >> 5;
    const int lane = threadIdx.x & 31;
    const int w    = blockIdx.x * 8 + warp;

    const int* trip; const float* g; const float* D; int T, t; float invT;
    if (w < TB)                { trip = t1; g = G1; D = g_Dz;  T = TB; t = w;                 invT = 1.0f / TB; }
    else if (w < TB + TL)      { trip = t2; g = G2; D = g_Dll; T = TL; t = w - TB;            invT = 1.0f / TL; }
    else if (w < 2*TB + TL)    { trip = t3; g = G3; D = g_Dt;  T = TB; t = w - (TB + TL);     invT = 1.0f / TB; }
    else                       { trip = t4; g = G4; D = g_Dll; T = TL; t = w - (2*TB + TL);   invT = 1.0f / TL; }

    const int i = trip[t];
    const int j = trip[T + t];
    const int k = trip[2 * T + t];
    const float* __restrict__ di = D + (size_t)i * NP;
    const float* __restrict__ dj = D + (size_t)j * NP;
    const float* __restrict__ dk = D + (size_t)k * NP;
    const float* __restrict__ g0 = g + (size_t)t * NP;
    const float* __restrict__ g1 = g + ((size_t)T + t) * NP;
    const int base = lane * 8;

    float m[8];
    int idx0, idx1;

    // ---- phase A: di, dj, g0 -> max_ij, argmax0 ----
    {
        float4 a0 = *(const float4*)(di + base), a1 = *(const float4*)(di + base + 4);
        float4 b0 = *(const float4*)(dj + base), b1 = *(const float4*)(dj + base + 4);
        float ev[8];
        ldg_stream8(g0 + base, ev);
        float av[8] = {a0.x, a0.y, a0.z, a0.w, a1.x, a1.y, a1.z, a1.w};
        float bv[8] = {b0.x, b0.y, b0.z, b0.w, b1.x, b1.y, b1.z, b1.w};
        float s0[8], lmax = -INFINITY;
        #pragma unroll
        for (int u = 0; u < 8; ++u) {
            m[u]  = fmaxf(av[u], bv[u]);
            s0[u] = fmaf(m[u], -10.0f, ev[u]);        // g - max/tau
            lmax  = fmaxf(lmax, s0[u]);
        }
        float wmax = iordu(__reduce_max_sync(0xffffffffu, ordu(lmax)));
        int loc = NP;                                 // sentinel
        #pragma unroll
        for (int u = 7; u >= 0; --u)
            if (s0[u] == wmax) loc = base + u;        // lowest u wins
        unsigned msk = __ballot_sync(0xffffffffu, loc < NP);
        idx0 = __shfl_sync(0xffffffffu, loc, __ffs(msk) - 1);
    }
    // ---- phase B: dk, g1 -> max_ijk, argmax1 ----
    {
        float4 c0 = *(const float4*)(dk + base), c1 = *(const float4*)(dk + base + 4);
        float fv[8];
        ldg_stream8(g1 + base, fv);
        float cv[8] = {c0.x, c0.y, c0.z, c0.w, c1.x, c1.y, c1.z, c1.w};
        float s1[8], lmax = -INFINITY;
        #pragma unroll
        for (int u = 0; u < 8; ++u) {
            float m2 = fmaxf(cv[u], m[u]);
            s1[u] = fmaf(m2, -10.0f, fv[u]);
            lmax  = fmaxf(lmax, s1[u]);
        }
        float wmax = iordu(__reduce_max_sync(0xffffffffu, ordu(lmax)));
        int loc = NP;
        #pragma unroll
        for (int u = 7; u >= 0; --u)
            if (s1[u] == wmax) loc = base + u;
        unsigned msk = __ballot_sync(0xffffffffu, loc < NP);
        idx1 = __shfl_sync(0xffffffffu, loc, __ffs(msk) - 1);
    }

    float hc = 0.0f;
    if (lane == 0 && idx0 != idx1) {                  // diff_lca gate
        float dia = di[idx0], dib = di[idx1];
        float dja = dj[idx0], djb = dj[idx1];
        float dka = dk[idx0], dkb = dk[idx1];
        float h = fmaxf(dia - dib + 0.1f, 0.0f)
                + fmaxf(dja - djb + 0.1f, 0.0f)
                + fmaxf(dkb - dka + 0.1f, 0.0f);
        hc = h * invT;
    }
    if (lane == 0) wsum[warp] = hc;
    __syncthreads();

    if (threadIdx.x == 0) {
        float s = 0.0f;
        #pragma unroll
        for (int q = 0; q < 8; ++q) s += wsum[q];
        atomicAdd(outp, s);                           // fire-and-forget
    }
}

// ---------------- launch -----------------------------------------------------
extern "C" void kernel_launch(void* const* d_in, const int* in_sizes, int n_in,
                              void* d_out, int out_size) {
    const float* z_s   = (const float*)d_in[0];
    const float* t_s   = (const float*)d_in[1];
    /* d_in[2] = y, unused */
    const float* lcas  = (const float*)d_in[3];
    const int*   trip1 = (const int*)d_in[4];
    const int*   trip2 = (const int*)d_in[5];
    const int*   trip3 = (const int*)d_in[6];
    const int*   trip4 = (const int*)d_in[7];
    const float* g1    = (const float*)d_in[8];
    const float* g2    = (const float*)d_in[9];
    const float* g3    = (const float*)d_in[10];
    const float* g4    = (const float*)d_in[11];

    k_dist_all<<<288, 256>>>(lcas, z_s, t_s, (float*)d_out);
    k_ghhc_all<<<NGBLK, 256>>>(trip1, trip2, trip3, trip4,
                               g1, g2, g3, g4, (float*)d_out);
}